// round 16
// baseline (speedup 1.0000x reference)
#include <cuda_runtime.h>
#include <cuda_fp16.h>
#include <cstdint>
#include <math.h>

#define B_    8
#define NPT   8192
#define MPT   2048
#define C_    256
#define H_    512
#define NTOT  (B_*NPT)

// GEMM tiling: BM=128, BN=128, BK=64 halves, rows 64 halves (128 B), XOR-swizzled
#define A_TH    8192
#define B_TH    8192
#define STG_H   (A_TH + B_TH)
#define NST     3
#define HDR_B   128
#define SMB     (HDR_B + NST*STG_H*2)       // 98432 B -> 2 CTAs/SM

// ---------------- scratch ----------------
__device__ __align__(1024) __half g_Xt[(size_t)512 * 8 * B_TH];
__device__ __align__(1024) __half g_Yt[(size_t)512 * 8 * B_TH];
__device__ __align__(1024) __half g_W1t[4 * 8 * A_TH];
__device__ __align__(1024) __half g_W2t[4 * 8 * A_TH];
__device__ __align__(16)   __half g_kfh[(size_t)B_ * MPT * C_];   // fp16 known_feats [b][m][c]
__device__ int    g_idx[NTOT * 3];
__device__ float  g_w[NTOT * 3];

__device__ __forceinline__ int kpos64(int l) {
    int p  = (l >> 1) & 7;
    int pp = ((p & 3) << 1) | (p >> 2);
    return (l & ~15) | (pp << 1) | (l & 1);
}
__device__ __forceinline__ int spos(int r, int l) {
    int b = kpos64(l);
    return ((((b >> 2) ^ ((r & 3) << 2)) << 2) | (b & 3));
}
__device__ __forceinline__ uint32_t smem_u32(const void* p) {
    uint32_t a;
    asm("{ .reg .u64 t; cvta.to.shared.u64 t, %1; cvt.u32.u64 %0, t; }" : "=r"(a) : "l"(p));
    return a;
}
__device__ __forceinline__ void bulk_cp(uint32_t dst, const void* src, uint32_t bytes, uint32_t mbar) {
    asm volatile("cp.async.bulk.shared::cta.global.mbarrier::complete_tx::bytes [%0], [%1], %2, [%3];"
                 :: "r"(dst), "l"(src), "r"(bytes), "r"(mbar) : "memory");
}
__device__ __forceinline__ void mbar_init(uint32_t a, uint32_t cnt) {
    asm volatile("mbarrier.init.shared.b64 [%0], %1;" :: "r"(a), "r"(cnt) : "memory");
}
__device__ __forceinline__ void mbar_expect(uint32_t a, uint32_t bytes) {
    asm volatile("mbarrier.arrive.expect_tx.shared.b64 _, [%0], %1;" :: "r"(a), "r"(bytes) : "memory");
}
__device__ __forceinline__ void mbar_wait(uint32_t a, uint32_t ph) {
    asm volatile("{\n\t.reg .pred P;\n\tWL%=:\n\t"
                 "mbarrier.try_wait.parity.acquire.cta.shared::cta.b64 P, [%0], %1, 0x989680;\n\t"
                 "@!P bra WL%=;\n\t}" :: "r"(a), "r"(ph) : "memory");
}

// ---------------- prep1: knn + W-tile + tr_kf (heterogeneous blocks) ----------------
// bid [0,256)        : knn (ALU-bound, scheduled first)
// bid [256,1280)     : W round/tile
// bid [1280,5376)    : tr_kf -> fp16
__global__ __launch_bounds__(256)
void prep1_kernel(const float* __restrict__ W1, const float* __restrict__ W2,
                  const float* __restrict__ kf,
                  const float* __restrict__ unknown, const float* __restrict__ known)
{
    __shared__ __align__(16) char shraw[MPT * 16];      // 32 KB
    const int bid = blockIdx.x;
    const int tid = threadIdx.x;

    if (bid < 256) {
        float4* k4 = (float4*)shraw;
        const int b = bid >> 5;
        const float* kb = known + (size_t)b * MPT * 3;
        for (int i = tid; i < MPT; i += 256) {
            float x = kb[i*3+0], y = kb[i*3+1], z = kb[i*3+2];
            k4[i] = make_float4(x, y, z, x*x + y*y + z*z);
        }
        __syncthreads();

        const int q = (bid & 31) * 256 + tid;
        const float* up = unknown + ((size_t)b * NPT + q) * 3;
        const float ux = up[0], uy = up[1], uz = up[2];
        const float ax = -2.f*ux, ay = -2.f*uy, az = -2.f*uz;
        const float uu = ux*ux + uy*uy + uz*uz;

        float d0 = 1e30f, d1 = 1e30f, d2 = 1e30f;
        int   i0 = 0,     i1 = 0,     i2 = 0;
        #pragma unroll 4
        for (int i = 0; i < MPT; i++) {
            float4 kv = k4[i];
            float d = fmaf(kv.x, ax, fmaf(kv.y, ay, fmaf(kv.z, az, kv.w)));
            if (d < d2) {
                if (d < d1) {
                    if (d < d0) { d2=d1; i2=i1; d1=d0; i1=i0; d0=d; i0=i; }
                    else        { d2=d1; i2=i1; d1=d;  i1=i; }
                } else          { d2=d;  i2=i; }
            }
        }
        d0 += uu; d1 += uu; d2 += uu;
        const float r0 = 1.f/(d0+1e-8f), r1 = 1.f/(d1+1e-8f), r2 = 1.f/(d2+1e-8f);
        const float s = 1.f/(r0+r1+r2);
        const int gi = b * NPT + q;
        g_idx[gi*3+0] = i0; g_idx[gi*3+1] = i1; g_idx[gi*3+2] = i2;
        g_w[gi*3+0] = r0*s; g_w[gi*3+1] = r1*s; g_w[gi*3+2] = r2*s;
        return;
    }

    if (bid < 256 + 1024) {
        int i = (bid - 256) * 256 + tid;
        int o = i >> 9, k = i & 511;
        int row = o & 127;
        size_t a = (size_t)((o >> 7) * 8 + (k >> 6)) * A_TH + row * 64 + spos(row, k & 63);
        g_W1t[a] = __float2half_rn(W1[i]);
        g_W2t[a] = __float2half_rn(W2[i]);
        return;
    }

    float (*t)[33] = (float(*)[33])shraw;
    const int x = tid & 31, y0 = tid >> 5;
    const int idx = bid - 256 - 1024;
    const int m0 = (idx & 63) * 32;
    const int c0 = ((idx >> 6) & 7) * 32;
    const int b  = idx >> 9;
    #pragma unroll
    for (int yy = 0; yy < 32; yy += 8)
        t[y0+yy][x] = kf[((size_t)b*C_ + c0+y0+yy)*MPT + m0 + x];
    __syncthreads();
    #pragma unroll
    for (int yy = 0; yy < 32; yy += 8)
        g_kfh[((size_t)b*MPT + m0 + y0+yy)*C_ + c0 + x] = __float2half_rn(t[x][y0+yy]);
}

// ---------------- prep2: interp + tr_uf (heterogeneous blocks) ----------------
// bid [0,2048)       : interp (L2-gather-bound, scheduled first; Xt ktiles 0..3)
// bid [2048,18432)   : tr_uf -> Xt ktiles 4..7 (DRAM-bound)
__global__ __launch_bounds__(256)
void prep2_kernel(const float* __restrict__ uf)
{
    __shared__ __align__(16) char shraw[17408];
    const int bid = blockIdx.x;
    const int tid = threadIdx.x;

    if (bid < 2048) {
        __half (*sbuf)[264] = (__half(*)[264])shraw;
        const int wid  = tid >> 5;
        const int lane = tid & 31;
        const int p0   = bid * 32;

        #pragma unroll
        for (int it = 0; it < 4; it++) {
            const int s = wid * 4 + it;
            const int p = p0 + s;
            const int b = p >> 13;

            const int   i0 = g_idx[p*3+0], i1 = g_idx[p*3+1], i2 = g_idx[p*3+2];
            const float w0 = g_w[p*3+0],   w1 = g_w[p*3+1],   w2 = g_w[p*3+2];

            const __half2* a2 = (const __half2*)(g_kfh + ((size_t)b*MPT + i0)*C_ + lane*8);
            const __half2* c2 = (const __half2*)(g_kfh + ((size_t)b*MPT + i1)*C_ + lane*8);
            const __half2* e2 = (const __half2*)(g_kfh + ((size_t)b*MPT + i2)*C_ + lane*8);

            __half2 ah[4], ch[4], eh[4];
            *(uint4*)ah = *(const uint4*)a2;
            *(uint4*)ch = *(const uint4*)c2;
            *(uint4*)eh = *(const uint4*)e2;

            __half* sp = &sbuf[s][(lane >> 3) * 64];
            const int base = (lane & 7) * 8;
            #pragma unroll
            for (int j = 0; j < 4; j++) {
                float2 av = __half22float2(ah[j]);
                float2 cv = __half22float2(ch[j]);
                float2 ev = __half22float2(eh[j]);
                float vx = w0*av.x + w1*cv.x + w2*ev.x;
                float vy = w0*av.y + w1*cv.y + w2*ev.y;
                const int pos = kpos64(base + 2*j);
                *(__half2*)(sp + pos) = __floats2half2_rn(vx, vy);
            }
        }
        __syncthreads();

        #pragma unroll
        for (int it = 0; it < 4; it++) {
            const int id  = it * 256 + tid;
            const int row = id >> 3;
            const int c   = id & 7;
            const int s   = row >> 2;
            const int kt  = row & 3;
            const int p   = p0 + s;
            const int r   = p & 127;
            const int xr  = (r & 3) << 2;
            uint4 val = *(const uint4*)(&sbuf[s][kt*64 + c*8]);
            __half* dst = g_Xt + (size_t)((p >> 7) * 8 + kt) * B_TH + r * 64 + (((2*c) ^ xr) << 2);
            *(uint4*)dst = val;
        }
        return;
    }

    float (*t)[33] = (float(*)[33])shraw;
    const int x = tid & 31, y0 = tid >> 5;
    const int idx = bid - 2048;
    const int j0 = (idx & 255) * 32;
    const int c0 = ((idx >> 8) & 7) * 32;
    const int b  = idx >> 11;
    #pragma unroll
    for (int yy = 0; yy < 32; yy += 8)
        t[y0+yy][x] = uf[((size_t)b*C_ + c0+y0+yy)*NPT + j0 + x];
    __syncthreads();
    const int ch = C_ + c0 + x;
    const int kt = ch >> 6;
    const int kl = ch & 63;
    #pragma unroll
    for (int yy = 0; yy < 32; yy += 8) {
        const int p = b * NPT + j0 + y0 + yy;
        const int row = p & 127;
        g_Xt[(size_t)((p >> 7) * 8 + kt) * B_TH + row * 64 + spos(row, kl)] =
            __float2half_rn(t[x][y0+yy]);
    }
}

// ---------------- fp16 mma.sync GEMM: BM=128 BN=128 BK=64, 256 thr, 2 CTAs/SM ----------------
__device__ __forceinline__ void mma_f16(float* c, uint32_t a0, uint32_t a1, uint32_t a2, uint32_t a3,
                                        uint32_t b0, uint32_t b1)
{
    asm volatile(
        "mma.sync.aligned.m16n8k16.row.col.f32.f16.f16.f32 "
        "{%0,%1,%2,%3}, {%4,%5,%6,%7}, {%8,%9}, {%0,%1,%2,%3};"
        : "+f"(c[0]), "+f"(c[1]), "+f"(c[2]), "+f"(c[3])
        : "r"(a0), "r"(a1), "r"(a2), "r"(a3), "r"(b0), "r"(b1));
}

__global__ __launch_bounds__(256, 2)
void gemm_tc(const __half* __restrict__ Wt, const __half* __restrict__ Bt, void* __restrict__ OutV,
             const float* __restrict__ G, const float* __restrict__ Bb,
             const float* __restrict__ Mu, const float* __restrict__ Va, int mode)
{
    extern __shared__ char smraw[];
    __half* smh = (__half*)(smraw + HDR_B);
    const uint32_t sbase = smem_u32(smraw);
    const int tid  = threadIdx.x;
    const int wid  = tid >> 5;
    const int lane = tid & 31;
    const int g    = lane >> 2;
    const int ctib = lane & 3;
    const int wm0  = (wid >> 2) * 64;
    const int wn0  = (wid & 3)  * 32;
    const int mblk = blockIdx.x;
    const int nblk = blockIdx.y;
    const int m0   = mblk * 128;
    const int n0   = nblk * 128;

    if (tid == 0) {
        mbar_init(sbase + 0, 1);
        mbar_init(sbase + 8, 1);
        mbar_init(sbase + 16, 1);
    }
    __syncthreads();

    const __half* Asrc = Wt + (size_t)mblk * 8 * A_TH;
    const __half* Bsrc = Bt + (size_t)nblk * 8 * B_TH;

    if (tid == 0) {
        #pragma unroll
        for (int s = 0; s < 2; s++) {
            uint32_t mb = sbase + s*8;
            uint32_t st = sbase + HDR_B + s*STG_H*2;
            mbar_expect(mb, STG_H*2);
            bulk_cp(st,           Asrc + (size_t)s*A_TH, A_TH*2, mb);
            bulk_cp(st + A_TH*2,  Bsrc + (size_t)s*B_TH, B_TH*2, mb);
        }
    }

    float acc[4][4][4];
    #pragma unroll
    for (int mt = 0; mt < 4; mt++)
        #pragma unroll
        for (int nt = 0; nt < 4; nt++)
            #pragma unroll
            for (int q = 0; q < 4; q++) acc[mt][nt][q] = 0.0f;

    const int gx = (g & 3) << 2;

    for (int kt = 0; kt < 8; kt++) {
        const int s = kt % NST;
        __syncthreads();
        if (tid == 0 && kt + 2 < 8) {
            const int s2 = (kt + 2) % NST;
            uint32_t mb = sbase + s2*8;
            uint32_t st = sbase + HDR_B + s2*STG_H*2;
            mbar_expect(mb, STG_H*2);
            bulk_cp(st,          Asrc + (size_t)(kt+2)*A_TH, A_TH*2, mb);
            bulk_cp(st + A_TH*2, Bsrc + (size_t)(kt+2)*B_TH, B_TH*2, mb);
        }
        mbar_wait(sbase + s*8, (kt / NST) & 1);

        const __half* sA = smh + s*STG_H;
        const __half* sB = sA + A_TH;

        #pragma unroll
        for (int g16 = 0; g16 < 4; g16++) {
            const int ua = ((ctib + 4*g16) ^ gx) * 4;
            uint2 alo[4], ahi[4], bfr[4];
            #pragma unroll
            for (int mt = 0; mt < 4; mt++) {
                const __half* pa = sA + (wm0 + mt*16 + g)*64 + ua;
                alo[mt] = *(const uint2*)pa;
                ahi[mt] = *(const uint2*)(pa + 8*64);
            }
            #pragma unroll
            for (int nt = 0; nt < 4; nt++)
                bfr[nt] = *(const uint2*)(sB + (wn0 + nt*8 + g)*64 + ua);

            #pragma unroll
            for (int mt = 0; mt < 4; mt++)
                #pragma unroll
                for (int nt = 0; nt < 4; nt++)
                    mma_f16(acc[mt][nt],
                            alo[mt].x, ahi[mt].x, alo[mt].y, ahi[mt].y,
                            bfr[nt].x, bfr[nt].y);
        }
    }
    __syncthreads();

    // -------- epilogue: BN + ReLU --------
    if (mode == 0) {
        __half* patch = (__half*)(smraw + HDR_B) + wid * 2304;
        #pragma unroll
        for (int mt = 0; mt < 4; mt++) {
            const int o0 = m0 + wm0 + mt*16 + g;
            const float sc0 = G[o0]   * rsqrtf(Va[o0]   + 1e-5f);
            const float sh0 = Bb[o0]   - Mu[o0]  * sc0;
            const float sc1 = G[o0+8] * rsqrtf(Va[o0+8] + 1e-5f);
            const float sh1 = Bb[o0+8] - Mu[o0+8] * sc1;
            const int ml  = kpos64(mt*16 + g);
            const int mlh = kpos64(mt*16 + g + 8);
            #pragma unroll
            for (int nt = 0; nt < 4; nt++) {
                const int nl = nt*8 + 2*ctib;
                patch[ nl   *72 + ml ] = __float2half_rn(fmaxf(fmaf(acc[mt][nt][0], sc0, sh0), 0.f));
                patch[(nl+1)*72 + ml ] = __float2half_rn(fmaxf(fmaf(acc[mt][nt][1], sc0, sh0), 0.f));
                patch[ nl   *72 + mlh] = __float2half_rn(fmaxf(fmaf(acc[mt][nt][2], sc1, sh1), 0.f));
                patch[(nl+1)*72 + mlh] = __float2half_rn(fmaxf(fmaf(acc[mt][nt][3], sc1, sh1), 0.f));
            }
        }
        __syncwarp();
        const int kt0 = (m0 + wm0) >> 6;
        __half* yb = (__half*)OutV + (size_t)(nblk * 8 + kt0) * B_TH + wn0 * 64;
        #pragma unroll
        for (int rr = 0; rr < 32; rr++) {
            const int off = (((lane >> 1) ^ ((rr & 3) << 2)) << 2) + (lane & 1) * 2;
            *(__half2*)(yb + rr*64 + off) = *(__half2*)(patch + rr*72 + lane*2);
        }
    } else {
        float* patch = (float*)(smraw + HDR_B) + wid * 2304;
        #pragma unroll
        for (int mt = 0; mt < 4; mt++) {
            const int o0 = m0 + wm0 + mt*16 + g;
            const float sc0 = G[o0]   * rsqrtf(Va[o0]   + 1e-5f);
            const float sh0 = Bb[o0]   - Mu[o0]  * sc0;
            const float sc1 = G[o0+8] * rsqrtf(Va[o0+8] + 1e-5f);
            const float sh1 = Bb[o0+8] - Mu[o0+8] * sc1;
            const int ml = mt*16 + g;
            #pragma unroll
            for (int nt = 0; nt < 4; nt++) {
                const int nl = nt*8 + 2*ctib;
                patch[ ml   *36 + nl  ] = fmaxf(fmaf(acc[mt][nt][0], sc0, sh0), 0.f);
                patch[ ml   *36 + nl+1] = fmaxf(fmaf(acc[mt][nt][1], sc0, sh0), 0.f);
                patch[(ml+8)*36 + nl  ] = fmaxf(fmaf(acc[mt][nt][2], sc1, sh1), 0.f);
                patch[(ml+8)*36 + nl+1] = fmaxf(fmaf(acc[mt][nt][3], sc1, sh1), 0.f);
            }
        }
        __syncwarp();
        const int b  = n0 >> 13;
        const int j0 = (n0 & (NPT-1)) + wn0;
        float* ob = (float*)OutV + ((size_t)b * H_ + m0 + wm0) * NPT + j0;
        #pragma unroll
        for (int r = 0; r < 64; r++)
            ob[(size_t)r * NPT + lane] = patch[r*36 + lane];
    }
}

// ---------------- launch ----------------
extern "C" void kernel_launch(void* const* d_in, const int* in_sizes, int n_in,
                              void* d_out, int out_size)
{
    const float* unknown      = (const float*)d_in[0];
    const float* known        = (const float*)d_in[1];
    const float* unknow_feats = (const float*)d_in[2];
    const float* known_feats  = (const float*)d_in[3];
    const float* W1 = (const float*)d_in[4];
    const float* g1 = (const float*)d_in[5];
    const float* b1 = (const float*)d_in[6];
    const float* m1 = (const float*)d_in[7];
    const float* v1 = (const float*)d_in[8];
    const float* W2 = (const float*)d_in[9];
    const float* g2 = (const float*)d_in[10];
    const float* b2 = (const float*)d_in[11];
    const float* m2 = (const float*)d_in[12];
    const float* v2 = (const float*)d_in[13];
    float* out = (float*)d_out;

    __half* Xt;  cudaGetSymbolAddress((void**)&Xt,  g_Xt);
    __half* Yt;  cudaGetSymbolAddress((void**)&Yt,  g_Yt);
    __half* W1t; cudaGetSymbolAddress((void**)&W1t, g_W1t);
    __half* W2t; cudaGetSymbolAddress((void**)&W2t, g_W2t);

    cudaFuncSetAttribute(gemm_tc, cudaFuncAttributeMaxDynamicSharedMemorySize, SMB);

    prep1_kernel<<<256 + 1024 + 4096, 256>>>(W1, W2, known_feats, unknown, known);
    prep2_kernel<<<2048 + 16384, 256>>>(unknow_feats);

    gemm_tc<<<dim3(4, 512), 256, SMB>>>(W1t, Xt, Yt,  g1, b1, m1, v1, 0);
    gemm_tc<<<dim3(4, 512), 256, SMB>>>(W2t, Yt, out, g2, b2, m2, v2, 1);

    (void)in_sizes; (void)n_in; (void)out_size;
}

// round 17
// speedup vs baseline: 1.1095x; 1.1095x over previous
#include <cuda_runtime.h>
#include <cuda_fp16.h>
#include <cstdint>
#include <math.h>

#define B_    8
#define NPT   8192
#define MPT   2048
#define C_    256
#define H_    512
#define NTOT  (B_*NPT)

// GEMM tiling: BM=128, BN=128, BK=64 halves, rows 64 halves (128 B), XOR-swizzled
#define A_TH    8192
#define B_TH    8192
#define STG_H   (A_TH + B_TH)
#define NST     3
#define HDR_B   128
#define SMB     (HDR_B + NST*STG_H*2)       // 98432 B -> 2 CTAs/SM

// ---------------- scratch ----------------
__device__ __align__(1024) __half g_Xt[(size_t)512 * 8 * B_TH];
__device__ __align__(1024) __half g_Yt[(size_t)512 * 8 * B_TH];
__device__ __align__(1024) __half g_W1t[4 * 8 * A_TH];
__device__ __align__(1024) __half g_W2t[4 * 8 * A_TH];
__device__ __align__(16)   __half g_kfh[(size_t)B_ * MPT * C_];   // fp16 known_feats [b][m][c]
__device__ int    g_idx[NTOT * 3];
__device__ float  g_w[NTOT * 3];

__device__ __forceinline__ int kpos64(int l) {
    int p  = (l >> 1) & 7;
    int pp = ((p & 3) << 1) | (p >> 2);
    return (l & ~15) | (pp << 1) | (l & 1);
}
__device__ __forceinline__ int spos(int r, int l) {
    int b = kpos64(l);
    return ((((b >> 2) ^ ((r & 3) << 2)) << 2) | (b & 3));
}
__device__ __forceinline__ uint32_t smem_u32(const void* p) {
    uint32_t a;
    asm("{ .reg .u64 t; cvta.to.shared.u64 t, %1; cvt.u32.u64 %0, t; }" : "=r"(a) : "l"(p));
    return a;
}
__device__ __forceinline__ void bulk_cp(uint32_t dst, const void* src, uint32_t bytes, uint32_t mbar) {
    asm volatile("cp.async.bulk.shared::cta.global.mbarrier::complete_tx::bytes [%0], [%1], %2, [%3];"
                 :: "r"(dst), "l"(src), "r"(bytes), "r"(mbar) : "memory");
}
__device__ __forceinline__ void mbar_init(uint32_t a, uint32_t cnt) {
    asm volatile("mbarrier.init.shared.b64 [%0], %1;" :: "r"(a), "r"(cnt) : "memory");
}
__device__ __forceinline__ void mbar_expect(uint32_t a, uint32_t bytes) {
    asm volatile("mbarrier.arrive.expect_tx.shared.b64 _, [%0], %1;" :: "r"(a), "r"(bytes) : "memory");
}
__device__ __forceinline__ void mbar_wait(uint32_t a, uint32_t ph) {
    asm volatile("{\n\t.reg .pred P;\n\tWL%=:\n\t"
                 "mbarrier.try_wait.parity.acquire.cta.shared::cta.b64 P, [%0], %1, 0x989680;\n\t"
                 "@!P bra WL%=;\n\t}" :: "r"(a), "r"(ph) : "memory");
}

// ---------------- fused prep + knn (R15 topology; knn split-scan 2 thr/pt) ----------------
// bid [0,512)             : knn (ALU-bound, scheduled first; 128 pts/block, 2 thr/pt)
// bid [512,1536)          : W round/tile
// bid [1536,5632)         : tr_kf -> fp16
// bid [5632,22016)        : tr_uf -> X_tiled
__global__ __launch_bounds__(256)
void prep_kernel(const float* __restrict__ W1, const float* __restrict__ W2,
                 const float* __restrict__ kf, const float* __restrict__ uf,
                 const float* __restrict__ unknown, const float* __restrict__ known)
{
    __shared__ __align__(16) char shraw[MPT * 16];      // 32 KB
    const int bid = blockIdx.x;
    const int tid = threadIdx.x;

    if (bid < 512) {
        // ---- knn: 2 threads per point, each scans half the candidates ----
        float4* k4 = (float4*)shraw;
        const int b = bid >> 6;                         // 64 blocks per batch
        const float* kb = known + (size_t)b * MPT * 3;
        for (int i = tid; i < MPT; i += 256) {
            float x = kb[i*3+0], y = kb[i*3+1], z = kb[i*3+2];
            k4[i] = make_float4(x, y, z, x*x + y*y + z*z);
        }
        __syncthreads();

        const int q    = (bid & 63) * 128 + (tid >> 1);
        const int half = tid & 1;
        const float* up = unknown + ((size_t)b * NPT + q) * 3;
        const float ux = up[0], uy = up[1], uz = up[2];
        const float ax = -2.f*ux, ay = -2.f*uy, az = -2.f*uz;
        const float uu = ux*ux + uy*uy + uz*uz;

        float d0 = 1e30f, d1 = 1e30f, d2 = 1e30f;
        int   i0 = 0,     i1 = 0,     i2 = 0;
        const int ibeg = half * (MPT/2);
        #pragma unroll 4
        for (int ii = 0; ii < MPT/2; ii++) {
            const int i = ibeg + ii;
            float4 kv = k4[i];
            float d = fmaf(kv.x, ax, fmaf(kv.y, ay, fmaf(kv.z, az, kv.w)));
            if (d < d2) {
                if (d < d1) {
                    if (d < d0) { d2=d1; i2=i1; d1=d0; i1=i0; d0=d; i0=i; }
                    else        { d2=d1; i2=i1; d1=d;  i1=i; }
                } else          { d2=d;  i2=i; }
            }
        }
        // merge partner's top-3 (even thread = base, low indices -> strict < keeps tie order)
        float e0 = __shfl_xor_sync(0xFFFFFFFFu, d0, 1);
        float e1 = __shfl_xor_sync(0xFFFFFFFFu, d1, 1);
        float e2 = __shfl_xor_sync(0xFFFFFFFFu, d2, 1);
        int   j0 = __shfl_xor_sync(0xFFFFFFFFu, i0, 1);
        int   j1 = __shfl_xor_sync(0xFFFFFFFFu, i1, 1);
        int   j2 = __shfl_xor_sync(0xFFFFFFFFu, i2, 1);
        if (half == 0) {
            float dd[3] = {e0, e1, e2};
            int   jj[3] = {j0, j1, j2};
            #pragma unroll
            for (int m = 0; m < 3; m++) {
                float d = dd[m]; int i = jj[m];
                if (d < d2) {
                    if (d < d1) {
                        if (d < d0) { d2=d1; i2=i1; d1=d0; i1=i0; d0=d; i0=i; }
                        else        { d2=d1; i2=i1; d1=d;  i1=i; }
                    } else          { d2=d;  i2=i; }
                }
            }
            d0 += uu; d1 += uu; d2 += uu;
            const float r0 = 1.f/(d0+1e-8f), r1 = 1.f/(d1+1e-8f), r2 = 1.f/(d2+1e-8f);
            const float s = 1.f/(r0+r1+r2);
            const int gi = b * NPT + q;
            g_idx[gi*3+0] = i0; g_idx[gi*3+1] = i1; g_idx[gi*3+2] = i2;
            g_w[gi*3+0] = r0*s; g_w[gi*3+1] = r1*s; g_w[gi*3+2] = r2*s;
        }
        return;
    }

    if (bid < 512 + 1024) {
        int i = (bid - 512) * 256 + tid;
        int o = i >> 9, k = i & 511;
        int row = o & 127;
        size_t a = (size_t)((o >> 7) * 8 + (k >> 6)) * A_TH + row * 64 + spos(row, k & 63);
        g_W1t[a] = __float2half_rn(W1[i]);
        g_W2t[a] = __float2half_rn(W2[i]);
        return;
    }

    float (*t)[33] = (float(*)[33])shraw;
    const int x = tid & 31, y0 = tid >> 5;
    if (bid < 512 + 1024 + 4096) {
        const int idx = bid - 512 - 1024;
        const int m0 = (idx & 63) * 32;
        const int c0 = ((idx >> 6) & 7) * 32;
        const int b  = idx >> 9;
        #pragma unroll
        for (int yy = 0; yy < 32; yy += 8)
            t[y0+yy][x] = kf[((size_t)b*C_ + c0+y0+yy)*MPT + m0 + x];
        __syncthreads();
        #pragma unroll
        for (int yy = 0; yy < 32; yy += 8)
            g_kfh[((size_t)b*MPT + m0 + y0+yy)*C_ + c0 + x] = __float2half_rn(t[x][y0+yy]);
    } else {
        const int idx = bid - 512 - 1024 - 4096;
        const int j0 = (idx & 255) * 32;
        const int c0 = ((idx >> 8) & 7) * 32;
        const int b  = idx >> 11;
        #pragma unroll
        for (int yy = 0; yy < 32; yy += 8)
            t[y0+yy][x] = uf[((size_t)b*C_ + c0+y0+yy)*NPT + j0 + x];
        __syncthreads();
        const int ch = C_ + c0 + x;
        const int kt = ch >> 6;
        const int kl = ch & 63;
        #pragma unroll
        for (int yy = 0; yy < 32; yy += 8) {
            const int p = b * NPT + j0 + y0 + yy;
            const int row = p & 127;
            g_Xt[(size_t)((p >> 7) * 8 + kt) * B_TH + row * 64 + spos(row, kl)] =
                __float2half_rn(t[x][y0+yy]);
        }
    }
}

// ---------------- interpolate (fp16 gathers) -> X_tiled f16, coalesced stores ----------------
__global__ __launch_bounds__(256)
void interp_kernel()
{
    __shared__ __align__(16) __half sbuf[32][264];
    const int tid  = threadIdx.x;
    const int wid  = tid >> 5;
    const int lane = tid & 31;
    const int p0   = blockIdx.x * 32;

    #pragma unroll
    for (int it = 0; it < 4; it++) {
        const int s = wid * 4 + it;
        const int p = p0 + s;
        const int b = p >> 13;

        const int   i0 = g_idx[p*3+0], i1 = g_idx[p*3+1], i2 = g_idx[p*3+2];
        const float w0 = g_w[p*3+0],   w1 = g_w[p*3+1],   w2 = g_w[p*3+2];

        const __half2* a2 = (const __half2*)(g_kfh + ((size_t)b*MPT + i0)*C_ + lane*8);
        const __half2* c2 = (const __half2*)(g_kfh + ((size_t)b*MPT + i1)*C_ + lane*8);
        const __half2* e2 = (const __half2*)(g_kfh + ((size_t)b*MPT + i2)*C_ + lane*8);

        __half2 ah[4], ch[4], eh[4];
        *(uint4*)ah = *(const uint4*)a2;
        *(uint4*)ch = *(const uint4*)c2;
        *(uint4*)eh = *(const uint4*)e2;

        __half* sp = &sbuf[s][(lane >> 3) * 64];
        const int base = (lane & 7) * 8;
        #pragma unroll
        for (int j = 0; j < 4; j++) {
            float2 av = __half22float2(ah[j]);
            float2 cv = __half22float2(ch[j]);
            float2 ev = __half22float2(eh[j]);
            float vx = w0*av.x + w1*cv.x + w2*ev.x;
            float vy = w0*av.y + w1*cv.y + w2*ev.y;
            const int pos = kpos64(base + 2*j);
            *(__half2*)(sp + pos) = __floats2half2_rn(vx, vy);
        }
    }
    __syncthreads();

    #pragma unroll
    for (int it = 0; it < 4; it++) {
        const int id  = it * 256 + tid;
        const int row = id >> 3;
        const int c   = id & 7;
        const int s   = row >> 2;
        const int kt  = row & 3;
        const int p   = p0 + s;
        const int r   = p & 127;
        const int xr  = (r & 3) << 2;
        uint4 val = *(const uint4*)(&sbuf[s][kt*64 + c*8]);
        __half* dst = g_Xt + (size_t)((p >> 7) * 8 + kt) * B_TH + r * 64 + (((2*c) ^ xr) << 2);
        *(uint4*)dst = val;
    }
}

// ---------------- fp16 mma.sync GEMM: BM=128 BN=128 BK=64, 256 thr, 2 CTAs/SM ----------------
__device__ __forceinline__ void mma_f16(float* c, uint32_t a0, uint32_t a1, uint32_t a2, uint32_t a3,
                                        uint32_t b0, uint32_t b1)
{
    asm volatile(
        "mma.sync.aligned.m16n8k16.row.col.f32.f16.f16.f32 "
        "{%0,%1,%2,%3}, {%4,%5,%6,%7}, {%8,%9}, {%0,%1,%2,%3};"
        : "+f"(c[0]), "+f"(c[1]), "+f"(c[2]), "+f"(c[3])
        : "r"(a0), "r"(a1), "r"(a2), "r"(a3), "r"(b0), "r"(b1));
}

__global__ __launch_bounds__(256, 2)
void gemm_tc(const __half* __restrict__ Wt, const __half* __restrict__ Bt, void* __restrict__ OutV,
             const float* __restrict__ G, const float* __restrict__ Bb,
             const float* __restrict__ Mu, const float* __restrict__ Va, int mode)
{
    extern __shared__ char smraw[];
    __half* smh = (__half*)(smraw + HDR_B);
    const uint32_t sbase = smem_u32(smraw);
    const int tid  = threadIdx.x;
    const int wid  = tid >> 5;
    const int lane = tid & 31;
    const int g    = lane >> 2;
    const int ctib = lane & 3;
    const int wm0  = (wid >> 2) * 64;
    const int wn0  = (wid & 3)  * 32;
    const int mblk = blockIdx.x;
    const int nblk = blockIdx.y;
    const int m0   = mblk * 128;
    const int n0   = nblk * 128;

    if (tid == 0) {
        mbar_init(sbase + 0, 1);
        mbar_init(sbase + 8, 1);
        mbar_init(sbase + 16, 1);
    }
    __syncthreads();

    const __half* Asrc = Wt + (size_t)mblk * 8 * A_TH;
    const __half* Bsrc = Bt + (size_t)nblk * 8 * B_TH;

    if (tid == 0) {
        #pragma unroll
        for (int s = 0; s < 2; s++) {
            uint32_t mb = sbase + s*8;
            uint32_t st = sbase + HDR_B + s*STG_H*2;
            mbar_expect(mb, STG_H*2);
            bulk_cp(st,           Asrc + (size_t)s*A_TH, A_TH*2, mb);
            bulk_cp(st + A_TH*2,  Bsrc + (size_t)s*B_TH, B_TH*2, mb);
        }
    }

    float acc[4][4][4];
    #pragma unroll
    for (int mt = 0; mt < 4; mt++)
        #pragma unroll
        for (int nt = 0; nt < 4; nt++)
            #pragma unroll
            for (int q = 0; q < 4; q++) acc[mt][nt][q] = 0.0f;

    const int gx = (g & 3) << 2;

    for (int kt = 0; kt < 8; kt++) {
        const int s = kt % NST;
        __syncthreads();
        if (tid == 0 && kt + 2 < 8) {
            const int s2 = (kt + 2) % NST;
            uint32_t mb = sbase + s2*8;
            uint32_t st = sbase + HDR_B + s2*STG_H*2;
            mbar_expect(mb, STG_H*2);
            bulk_cp(st,          Asrc + (size_t)(kt+2)*A_TH, A_TH*2, mb);
            bulk_cp(st + A_TH*2, Bsrc + (size_t)(kt+2)*B_TH, B_TH*2, mb);
        }
        mbar_wait(sbase + s*8, (kt / NST) & 1);

        const __half* sA = smh + s*STG_H;
        const __half* sB = sA + A_TH;

        #pragma unroll
        for (int g16 = 0; g16 < 4; g16++) {
            const int ua = ((ctib + 4*g16) ^ gx) * 4;
            uint2 alo[4], ahi[4], bfr[4];
            #pragma unroll
            for (int mt = 0; mt < 4; mt++) {
                const __half* pa = sA + (wm0 + mt*16 + g)*64 + ua;
                alo[mt] = *(const uint2*)pa;
                ahi[mt] = *(const uint2*)(pa + 8*64);
            }
            #pragma unroll
            for (int nt = 0; nt < 4; nt++)
                bfr[nt] = *(const uint2*)(sB + (wn0 + nt*8 + g)*64 + ua);

            #pragma unroll
            for (int mt = 0; mt < 4; mt++)
                #pragma unroll
                for (int nt = 0; nt < 4; nt++)
                    mma_f16(acc[mt][nt],
                            alo[mt].x, ahi[mt].x, alo[mt].y, ahi[mt].y,
                            bfr[nt].x, bfr[nt].y);
        }
    }
    __syncthreads();

    // -------- epilogue: BN + ReLU --------
    if (mode == 0) {
        __half* patch = (__half*)(smraw + HDR_B) + wid * 2304;
        #pragma unroll
        for (int mt = 0; mt < 4; mt++) {
            const int o0 = m0 + wm0 + mt*16 + g;
            const float sc0 = G[o0]   * rsqrtf(Va[o0]   + 1e-5f);
            const float sh0 = Bb[o0]   - Mu[o0]  * sc0;
            const float sc1 = G[o0+8] * rsqrtf(Va[o0+8] + 1e-5f);
            const float sh1 = Bb[o0+8] - Mu[o0+8] * sc1;
            const int ml  = kpos64(mt*16 + g);
            const int mlh = kpos64(mt*16 + g + 8);
            #pragma unroll
            for (int nt = 0; nt < 4; nt++) {
                const int nl = nt*8 + 2*ctib;
                patch[ nl   *72 + ml ] = __float2half_rn(fmaxf(fmaf(acc[mt][nt][0], sc0, sh0), 0.f));
                patch[(nl+1)*72 + ml ] = __float2half_rn(fmaxf(fmaf(acc[mt][nt][1], sc0, sh0), 0.f));
                patch[ nl   *72 + mlh] = __float2half_rn(fmaxf(fmaf(acc[mt][nt][2], sc1, sh1), 0.f));
                patch[(nl+1)*72 + mlh] = __float2half_rn(fmaxf(fmaf(acc[mt][nt][3], sc1, sh1), 0.f));
            }
        }
        __syncwarp();
        const int kt0 = (m0 + wm0) >> 6;
        __half* yb = (__half*)OutV + (size_t)(nblk * 8 + kt0) * B_TH + wn0 * 64;
        #pragma unroll
        for (int rr = 0; rr < 32; rr++) {
            const int off = (((lane >> 1) ^ ((rr & 3) << 2)) << 2) + (lane & 1) * 2;
            *(__half2*)(yb + rr*64 + off) = *(__half2*)(patch + rr*72 + lane*2);
        }
    } else {
        float* patch = (float*)(smraw + HDR_B) + wid * 2304;
        #pragma unroll
        for (int mt = 0; mt < 4; mt++) {
            const int o0 = m0 + wm0 + mt*16 + g;
            const float sc0 = G[o0]   * rsqrtf(Va[o0]   + 1e-5f);
            const float sh0 = Bb[o0]   - Mu[o0]  * sc0;
            const float sc1 = G[o0+8] * rsqrtf(Va[o0+8] + 1e-5f);
            const float sh1 = Bb[o0+8] - Mu[o0+8] * sc1;
            const int ml = mt*16 + g;
            #pragma unroll
            for (int nt = 0; nt < 4; nt++) {
                const int nl = nt*8 + 2*ctib;
                patch[ ml   *36 + nl  ] = fmaxf(fmaf(acc[mt][nt][0], sc0, sh0), 0.f);
                patch[ ml   *36 + nl+1] = fmaxf(fmaf(acc[mt][nt][1], sc0, sh0), 0.f);
                patch[(ml+8)*36 + nl  ] = fmaxf(fmaf(acc[mt][nt][2], sc1, sh1), 0.f);
                patch[(ml+8)*36 + nl+1] = fmaxf(fmaf(acc[mt][nt][3], sc1, sh1), 0.f);
            }
        }
        __syncwarp();
        const int b  = n0 >> 13;
        const int j0 = (n0 & (NPT-1)) + wn0;
        float* ob = (float*)OutV + ((size_t)b * H_ + m0 + wm0) * NPT + j0;
        #pragma unroll
        for (int r = 0; r < 64; r++)
            ob[(size_t)r * NPT + lane] = patch[r*36 + lane];
    }
}

// ---------------- launch ----------------
extern "C" void kernel_launch(void* const* d_in, const int* in_sizes, int n_in,
                              void* d_out, int out_size)
{
    const float* unknown      = (const float*)d_in[0];
    const float* known        = (const float*)d_in[1];
    const float* unknow_feats = (const float*)d_in[2];
    const float* known_feats  = (const float*)d_in[3];
    const float* W1 = (const float*)d_in[4];
    const float* g1 = (const float*)d_in[5];
    const float* b1 = (const float*)d_in[6];
    const float* m1 = (const float*)d_in[7];
    const float* v1 = (const float*)d_in[8];
    const float* W2 = (const float*)d_in[9];
    const float* g2 = (const float*)d_in[10];
    const float* b2 = (const float*)d_in[11];
    const float* m2 = (const float*)d_in[12];
    const float* v2 = (const float*)d_in[13];
    float* out = (float*)d_out;

    __half* Xt;  cudaGetSymbolAddress((void**)&Xt,  g_Xt);
    __half* Yt;  cudaGetSymbolAddress((void**)&Yt,  g_Yt);
    __half* W1t; cudaGetSymbolAddress((void**)&W1t, g_W1t);
    __half* W2t; cudaGetSymbolAddress((void**)&W2t, g_W2t);

    cudaFuncSetAttribute(gemm_tc, cudaFuncAttributeMaxDynamicSharedMemorySize, SMB);

    prep_kernel<<<512 + 1024 + 4096 + 16384, 256>>>(W1, W2, known_feats, unknow_feats,
                                                    unknown, known);
    interp_kernel<<<NTOT/32, 256>>>();

    gemm_tc<<<dim3(4, 512), 256, SMB>>>(W1t, Xt, Yt,  g1, b1, m1, v1, 0);
    gemm_tc<<<dim3(4, 512), 256, SMB>>>(W2t, Yt, out, g2, b2, m2, v2, 1);

    (void)in_sizes; (void)n_in; (void)out_size;
}